// round 8
// baseline (speedup 1.0000x reference)
#include <cuda_runtime.h>
#include <cuda_bf16.h>
#include <cstdint>

// Conv2D 3x3 s1 p1 -> implicit GEMM, mma.sync bf16 m16n8k16, 3-term hi/lo
// (hh + hl + lh). R8 = R4-proven pipeline (materialized im2col SMEM images,
// cp.async.bulk + mbarrier, pure-HMMA mainloop) with:
//   (1) grid swap: mblk fastest -> both consumers of a B tile are
//       wave-adjacent, second read is L2-served (-491MB DRAM),
//   (2) 3-stage pipeline (was 2) to cover load latency/jitter.
// TMA-tensor and tcgen05 paths are abandoned: harness compiles plain
// compute_103 (no 'a'); tcgen05 fails at ptxas, TMA-tensor traps at runtime.

namespace {
constexpr int IN_C = 128, OUT_C = 256, H = 56, W = 56, BATCH = 32;
constexpr int HW   = H * W;            // 3136
constexpr int Ndim = BATCH * HW;       // 100352
constexpr int Kdim = IN_C * 9;         // 1152

constexpr int BM = 128, BK = 32;
constexpr int NCH  = Kdim / BK;        // 36 chunks; chunk c: tap r=c>>2, icb=(c&3)*32
constexpr int MBLK = OUT_C / BM;       // 2
constexpr int NT   = Ndim / 128;       // 784

constexpr int A_HALF = BM * 80;        // [128 m][32 k] bf16, 80B padded rows
constexpr int A_CH   = 2 * A_HALF;     // 20480 (hi+lo)
constexpr int B_HALF = BK * 272;       // [32 k][128 n] bf16, 272B padded rows
constexpr int B_CH   = 2 * B_HALF;     // 17408
constexpr int STAGE  = A_CH + B_CH;    // 37888
constexpr int OFF_A  = 0;
constexpr int OFF_B  = A_CH;
constexpr int NSTG   = 3;
constexpr int SM_BAR = NSTG * STAGE;   // 113664
constexpr int SMEM_TOTAL = SM_BAR + 64;  // 113728 -> 2 CTAs/SM
}  // namespace

// device scratch (allocation-free rule)
__device__ __align__(16) unsigned char g_A[(size_t)MBLK * NCH * A_CH];   // 1.4MB
__device__ __align__(16) unsigned char g_B[(size_t)NT * NCH * B_CH];     // 491MB

// ---------------- helpers ----------------
__device__ __forceinline__ uint32_t smem_u32(const void* p) {
    uint32_t a;
    asm("{ .reg .u64 t; cvta.to.shared.u64 t, %1; cvt.u32.u64 %0, t; }" : "=r"(a) : "l"(p));
    return a;
}
__device__ __forceinline__ void ldsm4(uint32_t r[4], uint32_t addr) {
    asm volatile("ldmatrix.sync.aligned.m8n8.x4.shared.b16 {%0,%1,%2,%3}, [%4];"
                 : "=r"(r[0]), "=r"(r[1]), "=r"(r[2]), "=r"(r[3]) : "r"(addr));
}
__device__ __forceinline__ void ldsm4t(uint32_t* r, uint32_t addr) {
    asm volatile("ldmatrix.sync.aligned.m8n8.x4.trans.shared.b16 {%0,%1,%2,%3}, [%4];"
                 : "=r"(r[0]), "=r"(r[1]), "=r"(r[2]), "=r"(r[3]) : "r"(addr));
}
__device__ __forceinline__ void mma_bf16(float acc[4], const uint32_t a[4],
                                         uint32_t b0, uint32_t b1) {
    asm volatile(
        "mma.sync.aligned.m16n8k16.row.col.f32.bf16.bf16.f32 "
        "{%0,%1,%2,%3}, {%4,%5,%6,%7}, {%8,%9}, {%0,%1,%2,%3};"
        : "+f"(acc[0]), "+f"(acc[1]), "+f"(acc[2]), "+f"(acc[3])
        : "r"(a[0]), "r"(a[1]), "r"(a[2]), "r"(a[3]), "r"(b0), "r"(b1));
}
__device__ __forceinline__ uint32_t pack2(__nv_bfloat16 a, __nv_bfloat16 b) {
    __nv_bfloat162 t(a, b);
    return *reinterpret_cast<uint32_t*>(&t);
}
#define MBAR_INIT(a, n)   asm volatile("mbarrier.init.shared.b64 [%0], %1;" :: "r"(a), "r"(n) : "memory")
#define MBAR_EXPECT(a, b) asm volatile("mbarrier.arrive.expect_tx.shared.b64 _, [%0], %1;" :: "r"(a), "r"(b) : "memory")
#define MBAR_ARRIVE(a)    asm volatile("mbarrier.arrive.shared.b64 _, [%0];" :: "r"(a) : "memory")
#define MBAR_INVAL(a)     asm volatile("mbarrier.inval.shared.b64 [%0];" :: "r"(a) : "memory")
__device__ __forceinline__ void mbar_wait(uint32_t mbar, uint32_t parity) {
    asm volatile(
        "{\n\t.reg .pred P;\n"
        "WL_%=:\n\t"
        "mbarrier.try_wait.parity.acquire.cta.shared::cta.b64 P, [%0], %1, 0x989680;\n\t"
        "@P bra.uni WD_%=;\n\t"
        "bra.uni WL_%=;\n"
        "WD_%=:\n\t}"
        :: "r"(mbar), "r"(parity) : "memory");
}
__device__ __forceinline__ void bulk_g2s(uint32_t dst, const void* src, uint32_t bytes, uint32_t mbar) {
    asm volatile(
        "cp.async.bulk.shared::cluster.global.mbarrier::complete_tx::bytes [%0], [%1], %2, [%3];"
        :: "r"(dst), "l"(src), "r"(bytes), "r"(mbar) : "memory");
}
__device__ __forceinline__ void split_bf16(float v, __nv_bfloat16& h, __nv_bfloat16& l) {
    h = __float2bfloat16(v);
    l = __float2bfloat16(v - __bfloat162float(h));
}

// ---------------- prep: weights -> k-reordered SMEM-image bf16 hi/lo -------
__global__ void prep_weights(const float* __restrict__ Wk) {
    int idx = blockIdx.x * blockDim.x + threadIdx.x;
    if (idx >= OUT_C * NCH * 4) return;
    int kkg = idx & 3;
    int c   = (idx >> 2) % NCH;
    int m   = idx / (4 * NCH);
    int r   = c >> 2;
    int icb = (c & 3) * 32 + kkg * 8;

    const float* src = Wk + (size_t)m * Kdim + r;      // orig k = ic*9 + r
    uint32_t hi[4], lo[4];
    #pragma unroll
    for (int p = 0; p < 4; ++p) {
        __nv_bfloat16 h0, l0, h1, l1;
        split_bf16(src[(icb + 2 * p) * 9], h0, l0);
        split_bf16(src[(icb + 2 * p + 1) * 9], h1, l1);
        hi[p] = pack2(h0, h1);
        lo[p] = pack2(l0, l1);
    }
    size_t base = ((size_t)(m >> 7) * NCH + c) * A_CH + (size_t)(m & 127) * 80 + kkg * 16;
    *reinterpret_cast<uint4*>(g_A + base)          = make_uint4(hi[0], hi[1], hi[2], hi[3]);
    *reinterpret_cast<uint4*>(g_A + base + A_HALF) = make_uint4(lo[0], lo[1], lo[2], lo[3]);
}

// ---------------- prep: im2col(x) -> SMEM-image bf16 hi/lo -----------------
__global__ __launch_bounds__(256)
void prep_im2col(const float* __restrict__ x) {
    const int c = blockIdx.x;          // chunk: one (kh,kw), 32 ic
    const int t = blockIdx.y;          // n tile
    const int tid = threadIdx.x;
    const int g  = tid & 15;           // n group of 8
    const int kk = tid >> 4;           // rows kk, kk+16

    const int r  = c >> 2;
    const int kh = r / 3, kw = r - kh * 3;
    const int icb = (c & 3) * 32;

    const int n0  = t * 128 + g * 8;   // 8-aligned => one image, one row
    const int ni  = n0 / HW;
    const int hw0 = n0 - ni * HW;
    const int oh  = hw0 / W;
    const int ow0 = hw0 - oh * W;
    const int ih  = oh + kh - 1;
    const bool rv = (unsigned)ih < (unsigned)H;

    const size_t tb = ((size_t)t * NCH + c) * B_CH;

    #pragma unroll
    for (int s = 0; s < 2; ++s) {
        const int row = kk + s * 16;
        const int ic  = icb + row;
        const float* src = x + (((size_t)ni * IN_C + ic) * H + ih) * W;
        uint32_t hi[4], lo[4];
        #pragma unroll
        for (int p = 0; p < 4; ++p) {
            float v0 = 0.f, v1 = 0.f;
            int iw0 = ow0 + kw - 1 + 2 * p;
            if (rv) {
                if ((unsigned)iw0 < (unsigned)W)       v0 = __ldg(src + iw0);
                if ((unsigned)(iw0 + 1) < (unsigned)W) v1 = __ldg(src + iw0 + 1);
            }
            __nv_bfloat16 h0, l0, h1, l1;
            split_bf16(v0, h0, l0);
            split_bf16(v1, h1, l1);
            hi[p] = pack2(h0, h1);
            lo[p] = pack2(l0, l1);
        }
        size_t o = tb + (size_t)row * 272 + g * 16;
        *reinterpret_cast<uint4*>(g_B + o)          = make_uint4(hi[0], hi[1], hi[2], hi[3]);
        *reinterpret_cast<uint4*>(g_B + o + B_HALF) = make_uint4(lo[0], lo[1], lo[2], lo[3]);
    }
}

// ---------------- GEMM: pure HMMA, 3-stage bulk-copy pipeline --------------
__global__ __launch_bounds__(256, 2)
void conv_mma2(const float* __restrict__ bias, float* __restrict__ out)
{
    extern __shared__ char smem[];
    const uint32_t sb = smem_u32(smem);
    const int tid = threadIdx.x, lane = tid & 31, wp = tid >> 5;
    const int warp_m = wp >> 2, warp_n = wp & 3;
    const int mblk = blockIdx.x, t = blockIdx.y;   // mblk fastest: B L2 reuse

    uint32_t full[NSTG], emp[NSTG];
    #pragma unroll
    for (int s = 0; s < NSTG; ++s) {
        full[s] = sb + SM_BAR + s * 8;
        emp[s]  = sb + SM_BAR + (NSTG + s) * 8;
    }
    if (tid == 0) {
        #pragma unroll
        for (int s = 0; s < NSTG; ++s) { MBAR_INIT(full[s], 1); MBAR_INIT(emp[s], 256); }
    }
    __syncthreads();

    const unsigned char* gA = g_A + (size_t)mblk * NCH * A_CH;
    const unsigned char* gB = g_B + (size_t)t * NCH * B_CH;

    auto load = [&](int c, int s) {
        uint32_t st = sb + s * STAGE;
        MBAR_EXPECT(full[s], STAGE);
        bulk_g2s(st + OFF_A, gA + (size_t)c * A_CH, A_CH, full[s]);
        bulk_g2s(st + OFF_B, gB + (size_t)c * B_CH, B_CH, full[s]);
    };
    if (tid == 0) { load(0, 0); load(1, 1); load(2, 2); }

    float acc[4][4][4];
    #pragma unroll
    for (int a = 0; a < 4; ++a)
        #pragma unroll
        for (int b = 0; b < 4; ++b)
            #pragma unroll
            for (int cc = 0; cc < 4; ++cc) acc[a][b][cc] = 0.f;

    const uint32_t a_lane = (warp_m * 64 + (lane & 15)) * 80 + (lane >> 4) * 16;
    const uint32_t b_lane = (lane & 15) * 272 + warp_n * 64 + (lane >> 4) * 16;

    int fp[NSTG] = {0, 0, 0}, ep[NSTG] = {0, 0, 0};
    for (int c = 0; c < NCH; ++c) {
        const int s = c % NSTG;
        mbar_wait(full[s], fp[s]); fp[s] ^= 1;

        const uint32_t ab = sb + s * STAGE + OFF_A + a_lane;
        const uint32_t bb = sb + s * STAGE + OFF_B + b_lane;
        #pragma unroll
        for (int ks = 0; ks < 2; ++ks) {
            uint32_t Bh[2][4], Bl[2][4];
            #pragma unroll
            for (int jh = 0; jh < 2; ++jh) {
                ldsm4t(Bh[jh], bb + ks * 4352 + jh * 32);
                ldsm4t(Bl[jh], bb + ks * 4352 + jh * 32 + B_HALF);
            }
            #pragma unroll
            for (int mt = 0; mt < 4; ++mt) {
                uint32_t Ah[4], Al[4];
                ldsm4(Ah, ab + mt * 1280 + ks * 32);
                ldsm4(Al, ab + mt * 1280 + ks * 32 + A_HALF);
                #pragma unroll
                for (int nt = 0; nt < 4; ++nt) {
                    uint32_t bh0 = Bh[nt >> 1][(nt & 1) * 2];
                    uint32_t bh1 = Bh[nt >> 1][(nt & 1) * 2 + 1];
                    uint32_t bl0 = Bl[nt >> 1][(nt & 1) * 2];
                    uint32_t bl1 = Bl[nt >> 1][(nt & 1) * 2 + 1];
                    mma_bf16(acc[mt][nt], Ah, bh0, bh1);   // hh
                    mma_bf16(acc[mt][nt], Ah, bl0, bl1);   // hl
                    mma_bf16(acc[mt][nt], Al, bh0, bh1);   // lh
                }
            }
        }
        MBAR_ARRIVE(emp[s]);
        if (tid == 0 && c + NSTG < NCH) {
            mbar_wait(emp[s], ep[s]); ep[s] ^= 1;
            load(c + NSTG, s);
        }
    }

    // ---- epilogue: bias + direct stores (layout proven since R3) ----
    #pragma unroll
    for (int mt = 0; mt < 4; ++mt) {
        int oc0 = mblk * BM + warp_m * 64 + mt * 16 + (lane >> 2);
        float b0 = bias[oc0], b1 = bias[oc0 + 8];
        #pragma unroll
        for (int nt = 0; nt < 4; ++nt) {
            int g  = t * 128 + warp_n * 32 + nt * 8 + (lane & 3) * 2;
            int ni = g / HW;
            int hw = g - ni * HW;
            float2 v0 = make_float2(acc[mt][nt][0] + b0, acc[mt][nt][1] + b0);
            float2 v1 = make_float2(acc[mt][nt][2] + b1, acc[mt][nt][3] + b1);
            *reinterpret_cast<float2*>(out + ((size_t)ni * OUT_C + oc0) * HW + hw)     = v0;
            *reinterpret_cast<float2*>(out + ((size_t)ni * OUT_C + oc0 + 8) * HW + hw) = v1;
        }
    }

    __syncthreads();
    if (tid == 0) {
        #pragma unroll
        for (int s = 0; s < NSTG; ++s) { MBAR_INVAL(full[s]); MBAR_INVAL(emp[s]); }
    }
}

// ---------------- launch ----------------
extern "C" void kernel_launch(void* const* d_in, const int* in_sizes, int n_in,
                              void* d_out, int out_size) {
    const float* x    = (const float*)d_in[0];
    const float* Wk   = (const float*)d_in[1];
    const float* bias = (const float*)d_in[2];
    float* out        = (float*)d_out;

    cudaFuncSetAttribute(conv_mma2, cudaFuncAttributeMaxDynamicSharedMemorySize, SMEM_TOTAL);

    prep_weights<<<(OUT_C * NCH * 4 + 255) / 256, 256>>>(Wk);
    prep_im2col<<<dim3(NCH, NT), 256>>>(x);
    conv_mma2<<<dim3(MBLK, NT), 256, SMEM_TOTAL>>>(bias, out);
}

// round 9
// speedup vs baseline: 1.3559x; 1.3559x over previous
#include <cuda_runtime.h>
#include <cuda_fp16.h>
#include <cstdint>

// Conv2D 3x3 s1 p1 -> implicit GEMM, mma.sync fp16 m16n8k16, 2-term split:
//   D = Wh*x + Wl*x   (W = Wh + Wl exactly in fp16 pair; x single fp16)
// Error comes only from x's fp16 rounding (~2^-11) -> rel_err ~4e-4 < 1e-3.
// R9: 33% less tensor work than the bf16 3-term scheme (R4/R8), B images
// halve. Preps merged into ONE kernel so ncu's fixed -s 5 -c 1 slot captures
// the GEMM. Mainloop: cp.async.bulk + mbarrier, 3 stages, no __syncthreads.

namespace {
constexpr int IN_C = 128, OUT_C = 256, H = 56, W = 56, BATCH = 32;
constexpr int HW   = H * W;            // 3136
constexpr int Ndim = BATCH * HW;       // 100352
constexpr int Kdim = IN_C * 9;         // 1152

constexpr int BM = 128, BK = 32;
constexpr int NCH  = Kdim / BK;        // 36 chunks; chunk c: tap r=c>>2, icb=(c&3)*32
constexpr int MBLK = OUT_C / BM;       // 2
constexpr int NT   = Ndim / 128;       // 784

constexpr int A_HALF = BM * 80;        // [128 m][32 k] fp16, 80B padded rows
constexpr int A_CH   = 2 * A_HALF;     // 20480 (Wh + Wl)
constexpr int B_CH   = BK * 272;       // [32 k][128 n] fp16 single, 272B rows = 8704
constexpr int STAGE  = A_CH + B_CH;    // 29184
constexpr int OFF_A  = 0;
constexpr int OFF_B  = A_CH;
constexpr int NSTG   = 3;
constexpr int SM_BAR = NSTG * STAGE;   // 87552
constexpr int SMEM_TOTAL = SM_BAR + 64;  // -> 2 CTAs/SM
}  // namespace

// device scratch (allocation-free rule)
__device__ __align__(16) unsigned char g_A[(size_t)MBLK * NCH * A_CH];   // 1.4MB
__device__ __align__(16) unsigned char g_B[(size_t)NT * NCH * B_CH];     // 246MB

// ---------------- helpers ----------------
__device__ __forceinline__ uint32_t smem_u32(const void* p) {
    uint32_t a;
    asm("{ .reg .u64 t; cvta.to.shared.u64 t, %1; cvt.u32.u64 %0, t; }" : "=r"(a) : "l"(p));
    return a;
}
__device__ __forceinline__ void ldsm4(uint32_t r[4], uint32_t addr) {
    asm volatile("ldmatrix.sync.aligned.m8n8.x4.shared.b16 {%0,%1,%2,%3}, [%4];"
                 : "=r"(r[0]), "=r"(r[1]), "=r"(r[2]), "=r"(r[3]) : "r"(addr));
}
__device__ __forceinline__ void ldsm4t(uint32_t* r, uint32_t addr) {
    asm volatile("ldmatrix.sync.aligned.m8n8.x4.trans.shared.b16 {%0,%1,%2,%3}, [%4];"
                 : "=r"(r[0]), "=r"(r[1]), "=r"(r[2]), "=r"(r[3]) : "r"(addr));
}
__device__ __forceinline__ void mma_fp16(float acc[4], const uint32_t a[4],
                                         uint32_t b0, uint32_t b1) {
    asm volatile(
        "mma.sync.aligned.m16n8k16.row.col.f32.f16.f16.f32 "
        "{%0,%1,%2,%3}, {%4,%5,%6,%7}, {%8,%9}, {%0,%1,%2,%3};"
        : "+f"(acc[0]), "+f"(acc[1]), "+f"(acc[2]), "+f"(acc[3])
        : "r"(a[0]), "r"(a[1]), "r"(a[2]), "r"(a[3]), "r"(b0), "r"(b1));
}
__device__ __forceinline__ uint32_t pack2h(__half a, __half b) {
    __half2 t(a, b);
    return *reinterpret_cast<uint32_t*>(&t);
}
#define MBAR_INIT(a, n)   asm volatile("mbarrier.init.shared.b64 [%0], %1;" :: "r"(a), "r"(n) : "memory")
#define MBAR_EXPECT(a, b) asm volatile("mbarrier.arrive.expect_tx.shared.b64 _, [%0], %1;" :: "r"(a), "r"(b) : "memory")
#define MBAR_ARRIVE(a)    asm volatile("mbarrier.arrive.shared.b64 _, [%0];" :: "r"(a) : "memory")
#define MBAR_INVAL(a)     asm volatile("mbarrier.inval.shared.b64 [%0];" :: "r"(a) : "memory")
__device__ __forceinline__ void mbar_wait(uint32_t mbar, uint32_t parity) {
    asm volatile(
        "{\n\t.reg .pred P;\n"
        "WL_%=:\n\t"
        "mbarrier.try_wait.parity.acquire.cta.shared::cta.b64 P, [%0], %1, 0x989680;\n\t"
        "@P bra.uni WD_%=;\n\t"
        "bra.uni WL_%=;\n"
        "WD_%=:\n\t}"
        :: "r"(mbar), "r"(parity) : "memory");
}
__device__ __forceinline__ void bulk_g2s(uint32_t dst, const void* src, uint32_t bytes, uint32_t mbar) {
    asm volatile(
        "cp.async.bulk.shared::cluster.global.mbarrier::complete_tx::bytes [%0], [%1], %2, [%3];"
        :: "r"(dst), "l"(src), "r"(bytes), "r"(mbar) : "memory");
}
__device__ __forceinline__ void split_fp16(float v, __half& h, __half& l) {
    h = __float2half(v);
    l = __float2half(v - __half2float(h));
}

// ---------------- merged prep: weights (y==NT) + im2col (y<NT) -------------
__global__ __launch_bounds__(256)
void prep_all(const float* __restrict__ x, const float* __restrict__ Wk) {
    const int c = blockIdx.x;          // chunk: one (kh,kw), 32 ic
    const int tid = threadIdx.x;
    const int r  = c >> 2;
    const int icb = (c & 3) * 32;

    if (blockIdx.y == NT) {
        // ---- weights: thread = one (c, m) -> full 32-k row, Wh + Wl ----
        const int m = blockIdx.z * 256 + tid;        // z: 0..0 (OUT_C=256)
        const float* src = Wk + (size_t)m * Kdim + r;   // orig k = ic*9 + r
        size_t base = ((size_t)(m >> 7) * NCH + c) * A_CH + (size_t)(m & 127) * 80;
        #pragma unroll
        for (int kkg = 0; kkg < 4; ++kkg) {
            uint32_t hi[4], lo[4];
            #pragma unroll
            for (int p = 0; p < 4; ++p) {
                int ic0 = icb + kkg * 8 + 2 * p;
                __half h0, l0, h1, l1;
                split_fp16(src[ic0 * 9], h0, l0);
                split_fp16(src[(ic0 + 1) * 9], h1, l1);
                hi[p] = pack2h(h0, h1);
                lo[p] = pack2h(l0, l1);
            }
            *reinterpret_cast<uint4*>(g_A + base + kkg * 16) =
                make_uint4(hi[0], hi[1], hi[2], hi[3]);
            *reinterpret_cast<uint4*>(g_A + base + kkg * 16 + A_HALF) =
                make_uint4(lo[0], lo[1], lo[2], lo[3]);
        }
        return;
    }

    // ---- im2col: x -> single fp16 SMEM-image ----
    const int t  = blockIdx.y;
    const int g  = tid & 15;           // n group of 8
    const int kk = tid >> 4;           // rows kk, kk+16

    const int kh = r / 3, kw = r - kh * 3;
    const int n0  = t * 128 + g * 8;   // 8-aligned => one image, one row
    const int ni  = n0 / HW;
    const int hw0 = n0 - ni * HW;
    const int oh  = hw0 / W;
    const int ow0 = hw0 - oh * W;
    const int ih  = oh + kh - 1;
    const bool rv = (unsigned)ih < (unsigned)H;

    const size_t tb = ((size_t)t * NCH + c) * B_CH;

    #pragma unroll
    for (int s = 0; s < 2; ++s) {
        const int row = kk + s * 16;
        const int ic  = icb + row;
        const float* src = x + (((size_t)ni * IN_C + ic) * H + ih) * W;
        uint32_t hv[4];
        #pragma unroll
        for (int p = 0; p < 4; ++p) {
            float v0 = 0.f, v1 = 0.f;
            int iw0 = ow0 + kw - 1 + 2 * p;
            if (rv) {
                if ((unsigned)iw0 < (unsigned)W)       v0 = __ldg(src + iw0);
                if ((unsigned)(iw0 + 1) < (unsigned)W) v1 = __ldg(src + iw0 + 1);
            }
            hv[p] = pack2h(__float2half(v0), __float2half(v1));
        }
        *reinterpret_cast<uint4*>(g_B + tb + (size_t)row * 272 + g * 16) =
            make_uint4(hv[0], hv[1], hv[2], hv[3]);
    }
}

// ---------------- GEMM: pure HMMA (2 MMAs per k16), 3-stage pipeline -------
__global__ __launch_bounds__(256, 2)
void conv_mma4(const float* __restrict__ bias, float* __restrict__ out)
{
    extern __shared__ char smem[];
    const uint32_t sb = smem_u32(smem);
    const int tid = threadIdx.x, lane = tid & 31, wp = tid >> 5;
    const int warp_m = wp >> 2, warp_n = wp & 3;
    const int mblk = blockIdx.x, t = blockIdx.y;   // mblk fastest: B L2 reuse

    uint32_t full[NSTG], emp[NSTG];
    #pragma unroll
    for (int s = 0; s < NSTG; ++s) {
        full[s] = sb + SM_BAR + s * 8;
        emp[s]  = sb + SM_BAR + (NSTG + s) * 8;
    }
    if (tid == 0) {
        #pragma unroll
        for (int s = 0; s < NSTG; ++s) { MBAR_INIT(full[s], 1); MBAR_INIT(emp[s], 256); }
    }
    __syncthreads();

    const unsigned char* gA = g_A + (size_t)mblk * NCH * A_CH;
    const unsigned char* gB = g_B + (size_t)t * NCH * B_CH;

    auto load = [&](int c, int s) {
        uint32_t st = sb + s * STAGE;
        MBAR_EXPECT(full[s], STAGE);
        bulk_g2s(st + OFF_A, gA + (size_t)c * A_CH, A_CH, full[s]);
        bulk_g2s(st + OFF_B, gB + (size_t)c * B_CH, B_CH, full[s]);
    };
    if (tid == 0) { load(0, 0); load(1, 1); load(2, 2); }

    float acc[4][4][4];
    #pragma unroll
    for (int a = 0; a < 4; ++a)
        #pragma unroll
        for (int b = 0; b < 4; ++b)
            #pragma unroll
            for (int cc = 0; cc < 4; ++cc) acc[a][b][cc] = 0.f;

    const uint32_t a_lane = (warp_m * 64 + (lane & 15)) * 80 + (lane >> 4) * 16;
    const uint32_t b_lane = (lane & 15) * 272 + warp_n * 64 + (lane >> 4) * 16;

    int fp[NSTG] = {0, 0, 0}, ep[NSTG] = {0, 0, 0};
    for (int c = 0; c < NCH; ++c) {
        const int s = c % NSTG;
        mbar_wait(full[s], fp[s]); fp[s] ^= 1;

        const uint32_t ab = sb + s * STAGE + OFF_A + a_lane;
        const uint32_t bb = sb + s * STAGE + OFF_B + b_lane;
        #pragma unroll
        for (int ks = 0; ks < 2; ++ks) {
            uint32_t Bv[2][4];
            #pragma unroll
            for (int jh = 0; jh < 2; ++jh)
                ldsm4t(Bv[jh], bb + ks * 4352 + jh * 32);
            #pragma unroll
            for (int mt = 0; mt < 4; ++mt) {
                uint32_t Ah[4], Al[4];
                ldsm4(Ah, ab + mt * 1280 + ks * 32);
                ldsm4(Al, ab + mt * 1280 + ks * 32 + A_HALF);
                #pragma unroll
                for (int nt = 0; nt < 4; ++nt) {
                    uint32_t b0 = Bv[nt >> 1][(nt & 1) * 2];
                    uint32_t b1 = Bv[nt >> 1][(nt & 1) * 2 + 1];
                    mma_fp16(acc[mt][nt], Ah, b0, b1);   // Wh * x
                    mma_fp16(acc[mt][nt], Al, b0, b1);   // Wl * x
                }
            }
        }
        MBAR_ARRIVE(emp[s]);
        if (tid == 0 && c + NSTG < NCH) {
            mbar_wait(emp[s], ep[s]); ep[s] ^= 1;
            load(c + NSTG, s);
        }
    }

    // ---- epilogue: bias + direct stores (layout proven since R3) ----
    #pragma unroll
    for (int mt = 0; mt < 4; ++mt) {
        int oc0 = mblk * BM + warp_m * 64 + mt * 16 + (lane >> 2);
        float b0 = bias[oc0], b1 = bias[oc0 + 8];
        #pragma unroll
        for (int nt = 0; nt < 4; ++nt) {
            int g  = t * 128 + warp_n * 32 + nt * 8 + (lane & 3) * 2;
            int ni = g / HW;
            int hw = g - ni * HW;
            float2 v0 = make_float2(acc[mt][nt][0] + b0, acc[mt][nt][1] + b0);
            float2 v1 = make_float2(acc[mt][nt][2] + b1, acc[mt][nt][3] + b1);
            *reinterpret_cast<float2*>(out + ((size_t)ni * OUT_C + oc0) * HW + hw)     = v0;
            *reinterpret_cast<float2*>(out + ((size_t)ni * OUT_C + oc0 + 8) * HW + hw) = v1;
        }
    }

    __syncthreads();
    if (tid == 0) {
        #pragma unroll
        for (int s = 0; s < NSTG; ++s) { MBAR_INVAL(full[s]); MBAR_INVAL(emp[s]); }
    }
}

// ---------------- launch ----------------
extern "C" void kernel_launch(void* const* d_in, const int* in_sizes, int n_in,
                              void* d_out, int out_size) {
    const float* x    = (const float*)d_in[0];
    const float* Wk   = (const float*)d_in[1];
    const float* bias = (const float*)d_in[2];
    float* out        = (float*)d_out;

    cudaFuncSetAttribute(conv_mma4, cudaFuncAttributeMaxDynamicSharedMemorySize, SMEM_TOTAL);

    // 2 kernels per call -> ncu's fixed slot captures the GEMM.
    prep_all<<<dim3(NCH, NT + 1, 1), 256>>>(x, Wk);
    conv_mma4<<<dim3(MBLK, NT), 256, SMEM_TOTAL>>>(bias, out);
}

// round 10
// speedup vs baseline: 1.7848x; 1.3163x over previous
#include <cuda_runtime.h>
#include <cuda_fp16.h>
#include <cstdint>

// Conv2D 3x3 s1 p1 -> implicit GEMM, mma.sync fp16 m16n8k16, SINGLE term:
//   D = fp16(W) * fp16(x)
// R9 measured one fp16 rounding source = 2.08e-4 rel_err; two independent
// sources combine to ~2.9e-4 -- 3.4x under the 1e-3 gate. Tensor work halves
// vs R9 (floor ~103us). Pipeline/layout identical to the proven R9 kernel.

namespace {
constexpr int IN_C = 128, OUT_C = 256, H = 56, W = 56, BATCH = 32;
constexpr int HW   = H * W;            // 3136
constexpr int Ndim = BATCH * HW;       // 100352
constexpr int Kdim = IN_C * 9;         // 1152

constexpr int BM = 128, BK = 32;
constexpr int NCH  = Kdim / BK;        // 36 chunks; chunk c: tap r=c>>2, icb=(c&3)*32
constexpr int MBLK = OUT_C / BM;       // 2
constexpr int NT   = Ndim / 128;       // 784

constexpr int A_CH = BM * 80;          // [128 m][32 k] fp16, 80B padded rows = 10240
constexpr int B_CH = BK * 272;         // [32 k][128 n] fp16, 272B rows = 8704
constexpr int STAGE  = A_CH + B_CH;    // 18944
constexpr int OFF_A  = 0;
constexpr int OFF_B  = A_CH;
constexpr int NSTG   = 3;
constexpr int SM_BAR = NSTG * STAGE;   // 56832
constexpr int SMEM_TOTAL = SM_BAR + 64;
}  // namespace

// device scratch (allocation-free rule)
__device__ __align__(16) unsigned char g_A[(size_t)MBLK * NCH * A_CH];   // 0.7MB
__device__ __align__(16) unsigned char g_B[(size_t)NT * NCH * B_CH];     // 246MB

// ---------------- helpers ----------------
__device__ __forceinline__ uint32_t smem_u32(const void* p) {
    uint32_t a;
    asm("{ .reg .u64 t; cvta.to.shared.u64 t, %1; cvt.u32.u64 %0, t; }" : "=r"(a) : "l"(p));
    return a;
}
__device__ __forceinline__ void ldsm4(uint32_t r[4], uint32_t addr) {
    asm volatile("ldmatrix.sync.aligned.m8n8.x4.shared.b16 {%0,%1,%2,%3}, [%4];"
                 : "=r"(r[0]), "=r"(r[1]), "=r"(r[2]), "=r"(r[3]) : "r"(addr));
}
__device__ __forceinline__ void ldsm4t(uint32_t* r, uint32_t addr) {
    asm volatile("ldmatrix.sync.aligned.m8n8.x4.trans.shared.b16 {%0,%1,%2,%3}, [%4];"
                 : "=r"(r[0]), "=r"(r[1]), "=r"(r[2]), "=r"(r[3]) : "r"(addr));
}
__device__ __forceinline__ void mma_fp16(float acc[4], const uint32_t a[4],
                                         uint32_t b0, uint32_t b1) {
    asm volatile(
        "mma.sync.aligned.m16n8k16.row.col.f32.f16.f16.f32 "
        "{%0,%1,%2,%3}, {%4,%5,%6,%7}, {%8,%9}, {%0,%1,%2,%3};"
        : "+f"(acc[0]), "+f"(acc[1]), "+f"(acc[2]), "+f"(acc[3])
        : "r"(a[0]), "r"(a[1]), "r"(a[2]), "r"(a[3]), "r"(b0), "r"(b1));
}
__device__ __forceinline__ uint32_t pack2h(__half a, __half b) {
    __half2 t(a, b);
    return *reinterpret_cast<uint32_t*>(&t);
}
#define MBAR_INIT(a, n)   asm volatile("mbarrier.init.shared.b64 [%0], %1;" :: "r"(a), "r"(n) : "memory")
#define MBAR_EXPECT(a, b) asm volatile("mbarrier.arrive.expect_tx.shared.b64 _, [%0], %1;" :: "r"(a), "r"(b) : "memory")
#define MBAR_ARRIVE(a)    asm volatile("mbarrier.arrive.shared.b64 _, [%0];" :: "r"(a) : "memory")
#define MBAR_INVAL(a)     asm volatile("mbarrier.inval.shared.b64 [%0];" :: "r"(a) : "memory")
__device__ __forceinline__ void mbar_wait(uint32_t mbar, uint32_t parity) {
    asm volatile(
        "{\n\t.reg .pred P;\n"
        "WL_%=:\n\t"
        "mbarrier.try_wait.parity.acquire.cta.shared::cta.b64 P, [%0], %1, 0x989680;\n\t"
        "@P bra.uni WD_%=;\n\t"
        "bra.uni WL_%=;\n"
        "WD_%=:\n\t}"
        :: "r"(mbar), "r"(parity) : "memory");
}
__device__ __forceinline__ void bulk_g2s(uint32_t dst, const void* src, uint32_t bytes, uint32_t mbar) {
    asm volatile(
        "cp.async.bulk.shared::cluster.global.mbarrier::complete_tx::bytes [%0], [%1], %2, [%3];"
        :: "r"(dst), "l"(src), "r"(bytes), "r"(mbar) : "memory");
}

// ---------------- merged prep: weights (y==NT) + im2col (y<NT) -------------
__global__ __launch_bounds__(256)
void prep_all(const float* __restrict__ x, const float* __restrict__ Wk) {
    const int c = blockIdx.x;          // chunk: one (kh,kw), 32 ic
    const int tid = threadIdx.x;
    const int r  = c >> 2;
    const int icb = (c & 3) * 32;

    if (blockIdx.y == NT) {
        // ---- weights: thread = one (c, m) -> full 32-k row, single fp16 ----
        const int m = tid;                              // 256 threads = OUT_C
        const float* src = Wk + (size_t)m * Kdim + r;   // orig k = ic*9 + r
        size_t base = ((size_t)(m >> 7) * NCH + c) * A_CH + (size_t)(m & 127) * 80;
        #pragma unroll
        for (int kkg = 0; kkg < 4; ++kkg) {
            uint32_t hv[4];
            #pragma unroll
            for (int p = 0; p < 4; ++p) {
                int ic0 = icb + kkg * 8 + 2 * p;
                hv[p] = pack2h(__float2half(src[ic0 * 9]),
                               __float2half(src[(ic0 + 1) * 9]));
            }
            *reinterpret_cast<uint4*>(g_A + base + kkg * 16) =
                make_uint4(hv[0], hv[1], hv[2], hv[3]);
        }
        return;
    }

    // ---- im2col: x -> single fp16 SMEM-image ----
    const int t  = blockIdx.y;
    const int g  = tid & 15;           // n group of 8
    const int kk = tid >> 4;           // rows kk, kk+16

    const int kh = r / 3, kw = r - kh * 3;
    const int n0  = t * 128 + g * 8;   // 8-aligned => one image, one row
    const int ni  = n0 / HW;
    const int hw0 = n0 - ni * HW;
    const int oh  = hw0 / W;
    const int ow0 = hw0 - oh * W;
    const int ih  = oh + kh - 1;
    const bool rv = (unsigned)ih < (unsigned)H;

    const size_t tb = ((size_t)t * NCH + c) * B_CH;

    #pragma unroll
    for (int s = 0; s < 2; ++s) {
        const int row = kk + s * 16;
        const int ic  = icb + row;
        const float* src = x + (((size_t)ni * IN_C + ic) * H + ih) * W;
        uint32_t hv[4];
        #pragma unroll
        for (int p = 0; p < 4; ++p) {
            float v0 = 0.f, v1 = 0.f;
            int iw0 = ow0 + kw - 1 + 2 * p;
            if (rv) {
                if ((unsigned)iw0 < (unsigned)W)       v0 = __ldg(src + iw0);
                if ((unsigned)(iw0 + 1) < (unsigned)W) v1 = __ldg(src + iw0 + 1);
            }
            hv[p] = pack2h(__float2half(v0), __float2half(v1));
        }
        *reinterpret_cast<uint4*>(g_B + tb + (size_t)row * 272 + g * 16) =
            make_uint4(hv[0], hv[1], hv[2], hv[3]);
    }
}

// ---------------- GEMM: pure HMMA (1 MMA per k16 per tile), 3 stages -------
__global__ __launch_bounds__(256, 2)
void conv_mma5(const float* __restrict__ bias, float* __restrict__ out)
{
    extern __shared__ char smem[];
    const uint32_t sb = smem_u32(smem);
    const int tid = threadIdx.x, lane = tid & 31, wp = tid >> 5;
    const int warp_m = wp >> 2, warp_n = wp & 3;
    const int mblk = blockIdx.x, t = blockIdx.y;   // mblk fastest: B L2 reuse

    uint32_t full[NSTG], emp[NSTG];
    #pragma unroll
    for (int s = 0; s < NSTG; ++s) {
        full[s] = sb + SM_BAR + s * 8;
        emp[s]  = sb + SM_BAR + (NSTG + s) * 8;
    }
    if (tid == 0) {
        #pragma unroll
        for (int s = 0; s < NSTG; ++s) { MBAR_INIT(full[s], 1); MBAR_INIT(emp[s], 256); }
    }
    __syncthreads();

    const unsigned char* gA = g_A + (size_t)mblk * NCH * A_CH;
    const unsigned char* gB = g_B + (size_t)t * NCH * B_CH;

    auto load = [&](int c, int s) {
        uint32_t st = sb + s * STAGE;
        MBAR_EXPECT(full[s], STAGE);
        bulk_g2s(st + OFF_A, gA + (size_t)c * A_CH, A_CH, full[s]);
        bulk_g2s(st + OFF_B, gB + (size_t)c * B_CH, B_CH, full[s]);
    };
    if (tid == 0) { load(0, 0); load(1, 1); load(2, 2); }

    float acc[4][4][4];
    #pragma unroll
    for (int a = 0; a < 4; ++a)
        #pragma unroll
        for (int b = 0; b < 4; ++b)
            #pragma unroll
            for (int cc = 0; cc < 4; ++cc) acc[a][b][cc] = 0.f;

    const uint32_t a_lane = (warp_m * 64 + (lane & 15)) * 80 + (lane >> 4) * 16;
    const uint32_t b_lane = (lane & 15) * 272 + warp_n * 64 + (lane >> 4) * 16;

    int fp[NSTG] = {0, 0, 0}, ep[NSTG] = {0, 0, 0};
    for (int c = 0; c < NCH; ++c) {
        const int s = c % NSTG;
        mbar_wait(full[s], fp[s]); fp[s] ^= 1;

        const uint32_t ab = sb + s * STAGE + OFF_A + a_lane;
        const uint32_t bb = sb + s * STAGE + OFF_B + b_lane;
        #pragma unroll
        for (int ks = 0; ks < 2; ++ks) {
            uint32_t Bv[2][4];
            #pragma unroll
            for (int jh = 0; jh < 2; ++jh)
                ldsm4t(Bv[jh], bb + ks * 4352 + jh * 32);
            #pragma unroll
            for (int mt = 0; mt < 4; ++mt) {
                uint32_t Av[4];
                ldsm4(Av, ab + mt * 1280 + ks * 32);
                #pragma unroll
                for (int nt = 0; nt < 4; ++nt) {
                    uint32_t b0 = Bv[nt >> 1][(nt & 1) * 2];
                    uint32_t b1 = Bv[nt >> 1][(nt & 1) * 2 + 1];
                    mma_fp16(acc[mt][nt], Av, b0, b1);
                }
            }
        }
        MBAR_ARRIVE(emp[s]);
        if (tid == 0 && c + NSTG < NCH) {
            mbar_wait(emp[s], ep[s]); ep[s] ^= 1;
            load(c + NSTG, s);
        }
    }

    // ---- epilogue: bias + direct stores (layout proven since R3) ----
    #pragma unroll
    for (int mt = 0; mt < 4; ++mt) {
        int oc0 = mblk * BM + warp_m * 64 + mt * 16 + (lane >> 2);
        float b0 = bias[oc0], b1 = bias[oc0 + 8];
        #pragma unroll
        for (int nt = 0; nt < 4; ++nt) {
            int g  = t * 128 + warp_n * 32 + nt * 8 + (lane & 3) * 2;
            int ni = g / HW;
            int hw = g - ni * HW;
            float2 v0 = make_float2(acc[mt][nt][0] + b0, acc[mt][nt][1] + b0);
            float2 v1 = make_float2(acc[mt][nt][2] + b1, acc[mt][nt][3] + b1);
            *reinterpret_cast<float2*>(out + ((size_t)ni * OUT_C + oc0) * HW + hw)     = v0;
            *reinterpret_cast<float2*>(out + ((size_t)ni * OUT_C + oc0 + 8) * HW + hw) = v1;
        }
    }

    __syncthreads();
    if (tid == 0) {
        #pragma unroll
        for (int s = 0; s < NSTG; ++s) { MBAR_INVAL(full[s]); MBAR_INVAL(emp[s]); }
    }
}

// ---------------- launch ----------------
extern "C" void kernel_launch(void* const* d_in, const int* in_sizes, int n_in,
                              void* d_out, int out_size) {
    const float* x    = (const float*)d_in[0];
    const float* Wk   = (const float*)d_in[1];
    const float* bias = (const float*)d_in[2];
    float* out        = (float*)d_out;

    cudaFuncSetAttribute(conv_mma5, cudaFuncAttributeMaxDynamicSharedMemorySize, SMEM_TOTAL);

    prep_all<<<dim3(NCH, NT + 1, 1), 256>>>(x, Wk);
    conv_mma5<<<dim3(MBLK, NT), 256, SMEM_TOTAL>>>(bias, out);
}